// round 15
// baseline (speedup 1.0000x reference)
#include <cuda_runtime.h>
#include <cuda_fp16.h>
#include <cstdint>

#define T_ 4
#define B_ 16
#define NN 1024
#define C_ 256
#define CH_ 1024
#define SC (B_*C_*NN)
#define SQK (B_*NN*512)
#define SCH (B_*CH_*NN)
#define FLCAP (1u<<21)
#define EPS_FLAG 4e-3f

// ---------------- scratch ----------------
__device__ __half g_xsT [(size_t)T_*SC];
__device__ __half g_qkT [(size_t)T_*SQK];
__device__ __half g_y0T [(size_t)T_*SC];
__device__ __half g_z0T [(size_t)T_*SC];
__device__ __half g_z1T [(size_t)T_*SCH];
__device__ float  g_x1  [(size_t)T_*SC];
__device__ __half g_pqk [512*256];    // hi only
__device__ __half g_pp  [256*256];    // hi only
__device__ __half g_pw1 [1024*256];   // hi only
__device__ __half g_pw2 [256*1024];   // hi only
__device__ uint32_t g_cnt[3];
__device__ uint32_t g_l0[FLCAP];
__device__ uint32_t g_l1[FLCAP];
__device__ uint32_t g_l2[FLCAP];

// ---------------- helpers ----------------
__device__ __forceinline__ uint32_t smem_u32(const void* p) {
    uint32_t a;
    asm("{ .reg .u64 t; cvta.to.shared.u64 t, %1; cvt.u32.u64 %0, t; }" : "=r"(a) : "l"(p));
    return a;
}
__device__ __forceinline__ void cpasync16(uint32_t dst, const void* src) {
    asm volatile("cp.async.cg.shared.global [%0], [%1], 16;" :: "r"(dst), "l"(src) : "memory");
}
__device__ __forceinline__ void cp_commit() { asm volatile("cp.async.commit_group;" ::: "memory"); }
template<int N> __device__ __forceinline__ void cp_wait() {
    asm volatile("cp.async.wait_group %0;" :: "n"(N) : "memory");
}
__device__ __forceinline__ void ldsm4(uint32_t& r0, uint32_t& r1, uint32_t& r2, uint32_t& r3, uint32_t addr) {
    asm volatile("ldmatrix.sync.aligned.m8n8.x4.shared.b16 {%0,%1,%2,%3}, [%4];"
                 : "=r"(r0), "=r"(r1), "=r"(r2), "=r"(r3) : "r"(addr));
}
__device__ __forceinline__ void mma16816(float* d, const uint32_t* a, uint32_t b0, uint32_t b1) {
    asm volatile("mma.sync.aligned.m16n8k16.row.col.f32.f16.f16.f32 "
                 "{%0,%1,%2,%3}, {%4,%5,%6,%7}, {%8,%9}, {%0,%1,%2,%3};"
                 : "+f"(d[0]), "+f"(d[1]), "+f"(d[2]), "+f"(d[3])
                 : "r"(a[0]), "r"(a[1]), "r"(a[2]), "r"(a[3]), "r"(b0), "r"(b1));
}

// packed-A element index: blocked 64(m) x 64(ke) fp16 tiles, SW128-swizzled.
__device__ __forceinline__ size_t blk_elem(int m, int ke, int nck) {
    int bm = m >> 6, rin = m & 63, kc = ke >> 6, c = ke & 63;
    uint32_t byte = (uint32_t)(rin * 128 + c * 2);
    byte ^= (byte >> 3) & 0x70;
    return ((size_t)bm * nck + kc) * 4096 + (byte >> 1);
}

// ---------------- fused prep: lif_t (blocks 0..2047) + weight pack (2048..4863) ----
__global__ void prep_kernel(const float* __restrict__ x,
                            const float* __restrict__ qw, const float* __restrict__ kw,
                            const float* __restrict__ pw, const float* __restrict__ w1,
                            const float* __restrict__ w2) {
    if (blockIdx.x < 2048) {
        // ---- LIF + transpose: fp32 [t,b,c,n] -> fp16 spikes [t,b,n,c] ----
        __shared__ __half st[4][32][72];
        int id = blockIdx.x;
        int n0 = (id & 31) * 32, c0 = ((id >> 5) & 3) * 64, b = id >> 7;
        int nl = threadIdx.x & 31, cg = threadIdx.x >> 5;
#pragma unroll
        for (int pass = 0; pass < 8; pass++) {
            int cl = pass * 8 + cg;
            int c = c0 + cl;
            float mem = 0.f;
#pragma unroll
            for (int t = 0; t < T_; t++) {
                float v = mem * 0.5f + x[((size_t)(t * B_ + b) * C_ + c) * NN + n0 + nl];
                float sp = (v >= 1.0f) ? 1.f : 0.f;
                st[t][nl][cl] = __float2half(sp);
                mem = v * (1.f - sp);
            }
        }
        __syncthreads();
        int rr = threadIdx.x >> 1, hf = threadIdx.x & 1;
        int t = rr >> 5, n = rr & 31;
        size_t row = ((size_t)(t * B_ + b) * NN + n0 + n) * C_ + c0 + hf * 32;
        uint4* d = (uint4*)(g_xsT + row);
        const uint4* s = (const uint4*)(&st[t][n][hf * 32]);
#pragma unroll
        for (int i = 0; i < 4; i++) d[i] = s[i];
    } else {
        // ---- weight pack (+ flag counter reset) ----
        int pid = blockIdx.x - 2048;
        if (pid == 0 && threadIdx.x < 3) g_cnt[threadIdx.x] = 0;
        int idx = pid * 256 + threadIdx.x;
        if (idx < 131072) {                        // qk hi-only: M=512, K=256, nck=4
            int m = idx >> 8, k = idx & 255;
            float w = (m < 256) ? qw[m * 256 + k] : kw[(m - 256) * 256 + k];
            g_pqk[blk_elem(m, k, 4)] = __float2half(w);
        } else if (idx < 196608) {                 // proj hi-only 256x256
            int i = idx - 131072; int m = i >> 8, k = i & 255;
            g_pp[blk_elem(m, k, 4)] = __float2half(pw[i]);
        } else if (idx < 458752) {                 // w1 hi-only 1024x256
            int i = idx - 196608; int m = i >> 8, k = i & 255;
            g_pw1[blk_elem(m, k, 4)] = __float2half(w1[i]);
        } else if (idx < 720896) {                 // w2 hi-only 256x1024, nck=16
            int i = idx - 458752; int m = i >> 10, k = i & 1023;
            g_pw2[blk_elem(m, k, 16)] = __float2half(w2[i]);
        }
    }
}

// ---------------- attention (R13-verbatim implementation) ----------------
__global__ void attn_kernel(const __half* __restrict__ qk, __half* __restrict__ y,
                            const float* __restrict__ alpha_p) {
    int idx = blockIdx.x * 256 + threadIdx.x;
    int h = idx & 7;
    int n = (idx >> 3) & 1023;
    int b = idx >> 13;
    float alpha = *alpha_p;
    size_t baseq = ((size_t)(b * NN + n)) * 512 + h * 32;
    size_t basey = ((size_t)(b * NN + n)) * C_ + h * 32;

    float qs[T_];
#pragma unroll
    for (int t = 0; t < T_; t++) {
        const __half2* p = (const __half2*)(qk + (size_t)t * SQK + baseq);
        float s = 0.f;
#pragma unroll
        for (int i = 0; i < 16; i++) {
            float2 f = __half22float2(p[i]);
            s += f.x + f.y;
        }
        qs[t] = s;
    }
    float ms[T_];
    ms[0] = qs[0];
#pragma unroll
    for (int t = 1; t < T_; t++) ms[t] = alpha * ms[t - 1] + (1.f - alpha) * qs[t - 1];

    float mem = 0.f;
#pragma unroll
    for (int t = 0; t < T_; t++) {
        float v = mem * 0.5f + (ms[t] + qs[t]);
        float sp = (v >= 0.5f) ? 1.f : 0.f;
        mem = v * (1.f - sp);
        const uint4* kp = (const uint4*)(qk + (size_t)t * SQK + baseq + 256);
        uint4* yp = (uint4*)(y + (size_t)t * SC + basey);
        if (sp != 0.f) {
#pragma unroll
            for (int i = 0; i < 4; i++) yp[i] = kp[i];
        } else {
            uint4 z = {0, 0, 0, 0};
#pragma unroll
            for (int i = 0; i < 4; i++) yp[i] = z;
        }
    }
}

// ---------------- exact repairs: one WARP per flagged element ----------------
__global__ void repair_qk(const __half* __restrict__ xsT,
                          const float* __restrict__ qw, const float* __restrict__ kw,
                          const float* __restrict__ qg, const float* __restrict__ qb,
                          const float* __restrict__ kg, const float* __restrict__ kb,
                          __half* __restrict__ qkT) {
    uint32_t cnt = g_cnt[0]; if (cnt > FLCAP) cnt = FLCAP;
    uint32_t gw = (blockIdx.x * 256 + threadIdx.x) >> 5;
    uint32_t nwarp = gridDim.x * 8;
    int lane = threadIdx.x & 31;
    for (uint32_t idx = gw; idx < cnt; idx += nwarp) {
        uint32_t pk = g_l0[idx];
        int b = pk >> 20, n = (pk >> 10) & 1023, m = pk & 1023;
        const float* wrow; float sc, sh;
        if (m < 256) { wrow = qw + (size_t)m * 256; sc = qg[m]; sh = qb[m]; }
        else         { wrow = kw + (size_t)(m - 256) * 256; sc = kg[m - 256]; sh = kb[m - 256]; }
        float4 w0 = *(const float4*)&wrow[lane * 8];
        float4 w1v = *(const float4*)&wrow[lane * 8 + 4];
        float mem = 0.f;
        for (int t = 0; t < T_; t++) {
            const __half2* xr = (const __half2*)(xsT + ((size_t)((t * B_ + b) * NN + n)) * C_) + lane * 4;
            float2 f0 = __half22float2(xr[0]);
            float2 f1 = __half22float2(xr[1]);
            float2 f2 = __half22float2(xr[2]);
            float2 f3 = __half22float2(xr[3]);
            float dot = f0.x * w0.x + f0.y * w0.y + f1.x * w0.z + f1.y * w0.w
                      + f2.x * w1v.x + f2.y * w1v.y + f3.x * w1v.z + f3.y * w1v.w;
#pragma unroll
            for (int o = 16; o; o >>= 1) dot += __shfl_xor_sync(0xFFFFFFFFu, dot, o);
            float v = dot * sc + sh;
            float u = mem * 0.5f + v;
            float sp = (u >= 1.f) ? 1.f : 0.f;
            mem = u * (1.f - sp);
            if (lane == 0)
                qkT[((size_t)((t * B_ + b) * NN + n)) * 512 + m] = __float2half(sp);
        }
    }
}

// proj repair: exact dot over y0T + bias/bn + x residual; patches x1 AND z0 spike.
__global__ void repair_pj(const __half* __restrict__ y0T, const float* __restrict__ pw,
                          const float* __restrict__ pbias,
                          const float* __restrict__ pg, const float* __restrict__ pb2,
                          const float* __restrict__ x,
                          float* __restrict__ x1, __half* __restrict__ z0T) {
    uint32_t cnt = g_cnt[1]; if (cnt > FLCAP) cnt = FLCAP;
    uint32_t gw = (blockIdx.x * 256 + threadIdx.x) >> 5;
    uint32_t nwarp = gridDim.x * 8;
    int lane = threadIdx.x & 31;
    for (uint32_t idx = gw; idx < cnt; idx += nwarp) {
        uint32_t pk = g_l1[idx];
        int b = pk >> 20, n = (pk >> 10) & 1023, m = pk & 1023;
        const float* wrow = pw + (size_t)m * 256;
        float pb = pbias[m], sc = pg[m], sh = pb2[m];
        float4 w0 = *(const float4*)&wrow[lane * 8];
        float4 w1v = *(const float4*)&wrow[lane * 8 + 4];
        float mem = 0.f;
        for (int t = 0; t < T_; t++) {
            const __half2* xr = (const __half2*)(y0T + ((size_t)((t * B_ + b) * NN + n)) * C_) + lane * 4;
            float2 f0 = __half22float2(xr[0]);
            float2 f1 = __half22float2(xr[1]);
            float2 f2 = __half22float2(xr[2]);
            float2 f3 = __half22float2(xr[3]);
            float dot = f0.x * w0.x + f0.y * w0.y + f1.x * w0.z + f1.y * w0.w
                      + f2.x * w1v.x + f2.y * w1v.y + f3.x * w1v.z + f3.y * w1v.w;
#pragma unroll
            for (int o = 16; o; o >>= 1) dot += __shfl_xor_sync(0xFFFFFFFFu, dot, o);
            size_t o = ((size_t)((t * B_ + b) * C_) + m) * NN + n;
            float v = (dot + pb) * sc + sh + x[o];
            float u = mem * 0.5f + v;
            float sp = (u >= 1.f) ? 1.f : 0.f;
            mem = u * (1.f - sp);
            if (lane == 0) {
                x1[o] = v;
                z0T[((size_t)((t * B_ + b) * NN + n)) * C_ + m] = __float2half(sp);
            }
        }
    }
}

__global__ void repair_w1(const __half* __restrict__ z0T, const float* __restrict__ w1,
                          const float* __restrict__ b1,
                          const float* __restrict__ g1, const float* __restrict__ bb1,
                          __half* __restrict__ z1T) {
    uint32_t cnt = g_cnt[2]; if (cnt > FLCAP) cnt = FLCAP;
    uint32_t gw = (blockIdx.x * 256 + threadIdx.x) >> 5;
    uint32_t nwarp = gridDim.x * 8;
    int lane = threadIdx.x & 31;
    for (uint32_t idx = gw; idx < cnt; idx += nwarp) {
        uint32_t pk = g_l2[idx];
        int b = pk >> 20, n = (pk >> 10) & 1023, m = pk & 1023;
        const float* wrow = w1 + (size_t)m * 256;
        float pb = b1[m], sc = g1[m], sh = bb1[m];
        float4 w0 = *(const float4*)&wrow[lane * 8];
        float4 w1v = *(const float4*)&wrow[lane * 8 + 4];
        float mem = 0.f;
        for (int t = 0; t < T_; t++) {
            const __half2* xr = (const __half2*)(z0T + ((size_t)((t * B_ + b) * NN + n)) * C_) + lane * 4;
            float2 f0 = __half22float2(xr[0]);
            float2 f1 = __half22float2(xr[1]);
            float2 f2 = __half22float2(xr[2]);
            float2 f3 = __half22float2(xr[3]);
            float dot = f0.x * w0.x + f0.y * w0.y + f1.x * w0.z + f1.y * w0.w
                      + f2.x * w1v.x + f2.y * w1v.y + f3.x * w1v.z + f3.y * w1v.w;
#pragma unroll
            for (int o = 16; o; o >>= 1) dot += __shfl_xor_sync(0xFFFFFFFFu, dot, o);
            float v = (dot + pb) * sc + sh;
            float u = mem * 0.5f + v;
            float sp = (u >= 1.f) ? 1.f : 0.f;
            mem = u * (1.f - sp);
            if (lane == 0)
                z1T[((size_t)((t * B_ + b) * NN + n)) * CH_ + m] = __float2half(sp);
        }
    }
}

// ---------------- fp16 HMMA GEMM, fused epilogues ----------------
// CTA 64(M) x 128(N); 8 warps 2m x 4n; 2 CTAs/SM; 3-stage 1-sync pipeline.
// EPI 0: bn + LIF -> spikes. EPI 1: affine + res -> fp32.
// EPI 2: EPI1 + LIF -> spikes. EPI 3: EPI0 + flags. EPI 4: EPI2 + flags.
// TSPLIT: grid z = t*B_+b, single timestep per CTA (only legal when no LIF).
#define OF_B   24576
#define OF_STG 73728
#define SMEM_SP 93184
#define SMEM_NF 74752

template<int CSRC, int COUT, int EPI, int DUAL, int TSPLIT>
__global__ __launch_bounds__(256, 2) void gemm_mma(
    const __half* __restrict__ pack, const __half* __restrict__ XT,
    float* __restrict__ outF, __half* __restrict__ outS,
    const float* __restrict__ bias1,
    const float* __restrict__ scale, const float* __restrict__ shift,
    const float* __restrict__ scale2, const float* __restrict__ shift2,
    const float* __restrict__ res, float thr,
    uint32_t* flcnt, uint32_t* fllist)
{
    extern __shared__ char smraw[];
    uint32_t smb0 = smem_u32(smraw);
    uint32_t smb = (smb0 + 1023u) & ~1023u;
    char* base = smraw + (smb - smb0);

    const bool WR_F32 = (EPI == 1 || EPI == 2 || EPI == 4);
    const bool WR_SPK = (EPI != 1);
    const bool FLAGS  = (EPI >= 3);

    const int NC = CSRC / 64;
    const int TT = TSPLIT ? 1 : T_;
    const int G = TT * NC;
    const int n0g = blockIdx.x * 128;
    const int m0g = blockIdx.y * 64;
    const int zb  = blockIdx.z;
    const int b   = TSPLIT ? (zb & (B_ - 1)) : zb;
    const int t0  = TSPLIT ? (zb >> 4) : 0;
    const int tid = threadIdx.x;
    const int wid = tid >> 5, lane = tid & 31;
    const int mw = (wid >> 2) * 32, nw = (wid & 3) * 32;
    const int r = lane >> 2, qn = lane & 3;

    const float* SCp = scale; const float* SHp = shift; int moff = m0g;
    if (DUAL && m0g >= 256) { SCp = scale2; SHp = shift2; moff = m0g - 256; }

    float pb[2][2], psc[2][2], psh[2][2];
#pragma unroll
    for (int mi = 0; mi < 2; mi++)
#pragma unroll
        for (int h = 0; h < 2; h++) {
            int ml = mw + mi * 16 + r + h * 8;
            pb[mi][h]  = bias1 ? bias1[m0g + ml] : 0.f;
            psc[mi][h] = SCp[moff + ml];
            psh[mi][h] = SHp[moff + ml];
        }

    float acc[2][4][4];
    float memv[2][4][4];
    uint32_t bmask = 0;
#pragma unroll
    for (int mi = 0; mi < 2; mi++)
#pragma unroll
        for (int j = 0; j < 4; j++)
#pragma unroll
            for (int e = 0; e < 4; e++) { acc[mi][j][e] = 0.f; memv[mi][j][e] = 0.f; }

    auto issue = [&](int g) {
        int t = t0 + g / NC, kc = g % NC;
        int buf = g % 3;
        const __half* asrc = pack + ((size_t)blockIdx.y * NC + kc) * 4096 + tid * 16;
        uint32_t adst = smb + buf * 8192 + tid * 32;
        cpasync16(adst, asrc);
        cpasync16(adst + 16, asrc + 8);
        int row = tid >> 1, hf = tid & 1;
        const __half* bsrc = XT + ((size_t)((t * B_ + b) * NN + n0g + row)) * CSRC + kc * 64 + hf * 32;
        uint32_t bb = smb + OF_B + buf * 16384;
#pragma unroll
        for (int i = 0; i < 4; i++) {
            uint32_t byte = (uint32_t)(row * 128 + hf * 64 + i * 16);
            byte ^= ((byte >> 3) & 0x70);
            cpasync16(bb + byte, bsrc + i * 8);
        }
        cp_commit();
    };

    issue(0); issue(1);
    for (int g = 0; g < G; g++) {
        cp_wait<1>();
        __syncthreads();
        if (g + 2 < G) issue(g + 2); else cp_commit();

        uint32_t aB = smb + (g % 3) * 8192;
        uint32_t bB = smb + OF_B + (g % 3) * 16384;
#pragma unroll
        for (int ks = 0; ks < 4; ks++) {
            uint32_t af[2][4], bf[2][4];
#pragma unroll
            for (int mi = 0; mi < 2; mi++) {
                uint32_t byte = (uint32_t)((mw + mi * 16 + (lane & 15)) * 128 +
                                           (ks * 16 + (lane >> 4) * 8) * 2);
                byte ^= ((byte >> 3) & 0x70);
                ldsm4(af[mi][0], af[mi][1], af[mi][2], af[mi][3], aB + byte);
            }
#pragma unroll
            for (int j2 = 0; j2 < 2; j2++) {
                uint32_t byte = (uint32_t)((nw + j2 * 16 + (lane & 15)) * 128 +
                                           (ks * 16 + (lane >> 4) * 8) * 2);
                byte ^= ((byte >> 3) & 0x70);
                ldsm4(bf[j2][0], bf[j2][1], bf[j2][2], bf[j2][3], bB + byte);
            }
#pragma unroll
            for (int mi = 0; mi < 2; mi++)
#pragma unroll
                for (int j = 0; j < 4; j++)
                    mma16816(acc[mi][j], af[mi], bf[j >> 1][j & 1], bf[j >> 1][(j & 1) + 2]);
        }

        if ((g % NC) == NC - 1) {
            int t = t0 + g / NC;
#pragma unroll
            for (int mi = 0; mi < 2; mi++)
#pragma unroll
                for (int h = 0; h < 2; h++) {
                    int ml = mw + mi * 16 + r + h * 8;
#pragma unroll
                    for (int j = 0; j < 4; j++) {
#pragma unroll
                        for (int eo = 0; eo < 2; eo++) {
                            int e = h * 2 + eo;
                            int nl = nw + j * 8 + qn * 2 + eo;
                            float v = (acc[mi][j][e] + pb[mi][h]) * psc[mi][h] + psh[mi][h];
                            acc[mi][j][e] = 0.f;
                            if (WR_F32) {
                                size_t o = ((size_t)((t * B_ + b) * COUT) + m0g + ml) * NN
                                         + n0g + nl;
                                v += res[o];
                                outF[o] = v;
                            }
                            if (WR_SPK) {
                                float u = memv[mi][j][e] * 0.5f + v;
                                float sp = (u >= thr) ? 1.f : 0.f;
                                memv[mi][j][e] = u * (1.f - sp);
                                if (FLAGS && fabsf(u - thr) < EPS_FLAG)
                                    bmask |= 1u << (mi * 16 + j * 4 + e);
                                *(__half*)(base + OF_STG + nl * 144 + ml * 2) = __float2half(sp);
                            }
                        }
                    }
                }
            if (WR_SPK) {
                __syncthreads();
                int row = tid >> 1, hf = tid & 1;
                const uint4* s4 = (const uint4*)(base + OF_STG + row * 144 + hf * 64);
                uint4* d4 = (uint4*)(outS + ((size_t)((t * B_ + b) * NN + n0g + row)) * COUT
                                           + m0g + hf * 32);
#pragma unroll
                for (int i = 0; i < 4; i++) d4[i] = s4[i];
            }
            if (FLAGS && t == T_ - 1 && bmask) {
#pragma unroll
                for (int bit = 0; bit < 32; bit++)
                    if ((bmask >> bit) & 1) {
                        int mi = bit >> 4, j = (bit >> 2) & 3, e = bit & 3;
                        int h = e >> 1, eo = e & 1;
                        int ml = mw + mi * 16 + r + h * 8;
                        int nl = nw + j * 8 + qn * 2 + eo;
                        uint32_t pk = ((uint32_t)b << 20) | ((uint32_t)(n0g + nl) << 10)
                                    | (uint32_t)(m0g + ml);
                        uint32_t pos = atomicAdd(flcnt, 1u);
                        if (pos < FLCAP) fllist[pos] = pk;
                    }
            }
        }
    }
}

// ---------------- launch ----------------
extern "C" void kernel_launch(void* const* d_in, const int* in_sizes, int n_in,
                              void* d_out, int out_size) {
    const float* x         = (const float*)d_in[0];
    const float* q_w       = (const float*)d_in[1];
    const float* q_g       = (const float*)d_in[2];
    const float* q_b       = (const float*)d_in[3];
    const float* k_w       = (const float*)d_in[4];
    const float* k_g       = (const float*)d_in[5];
    const float* k_b       = (const float*)d_in[6];
    const float* proj_w    = (const float*)d_in[7];
    const float* proj_bias = (const float*)d_in[8];
    const float* proj_g    = (const float*)d_in[9];
    const float* proj_b2   = (const float*)d_in[10];
    const float* mem_alpha = (const float*)d_in[11];
    const float* w1        = (const float*)d_in[12];
    const float* b1        = (const float*)d_in[13];
    const float* bn1_g     = (const float*)d_in[14];
    const float* bn1_b     = (const float*)d_in[15];
    const float* w2        = (const float*)d_in[16];
    const float* b2        = (const float*)d_in[17];
    const float* bn2_g     = (const float*)d_in[18];
    const float* bn2_b     = (const float*)d_in[19];
    float* out = (float*)d_out;

    __half *xsT, *qkT, *y0T, *z0T, *z1T, *pqk, *pp, *pw1, *pw2;
    float* x1;
    uint32_t *cnt, *l0, *l1, *l2;
    cudaGetSymbolAddress((void**)&xsT, g_xsT);
    cudaGetSymbolAddress((void**)&qkT, g_qkT);
    cudaGetSymbolAddress((void**)&y0T, g_y0T);
    cudaGetSymbolAddress((void**)&z0T, g_z0T);
    cudaGetSymbolAddress((void**)&z1T, g_z1T);
    cudaGetSymbolAddress((void**)&x1,  g_x1);
    cudaGetSymbolAddress((void**)&pqk, g_pqk);
    cudaGetSymbolAddress((void**)&pp,  g_pp);
    cudaGetSymbolAddress((void**)&pw1, g_pw1);
    cudaGetSymbolAddress((void**)&pw2, g_pw2);
    cudaGetSymbolAddress((void**)&cnt, g_cnt);
    cudaGetSymbolAddress((void**)&l0,  g_l0);
    cudaGetSymbolAddress((void**)&l1,  g_l1);
    cudaGetSymbolAddress((void**)&l2,  g_l2);

    cudaFuncSetAttribute(gemm_mma<256, 512, 3, 1, 0>,  cudaFuncAttributeMaxDynamicSharedMemorySize, SMEM_SP);
    cudaFuncSetAttribute(gemm_mma<256, 256, 4, 0, 0>,  cudaFuncAttributeMaxDynamicSharedMemorySize, SMEM_SP);
    cudaFuncSetAttribute(gemm_mma<256, 1024, 3, 0, 0>, cudaFuncAttributeMaxDynamicSharedMemorySize, SMEM_SP);
    cudaFuncSetAttribute(gemm_mma<1024, 256, 1, 0, 1>, cudaFuncAttributeMaxDynamicSharedMemorySize, SMEM_NF);

    dim3 gQK(8, 8, 16);
    dim3 gPJ(8, 4, 16);
    dim3 gW1(8, 16, 16);
    dim3 gW2(8, 4, 64);   // T-split: z = t*16+b (no LIF chain in w2 epilogue)

    // 1. fused prep: lif_t(x) + weight pack + counter reset (independent work)
    prep_kernel<<<4864, 256>>>(x, q_w, k_w, proj_w, w1, w2);
    // 2. merged q|k GEMM hi-only + bn + LIF + flags
    gemm_mma<256, 512, 3, 1, 0><<<gQK, 256, SMEM_SP>>>(pqk, xsT, nullptr, qkT,
        nullptr, q_g, q_b, k_g, k_b, nullptr, 1.f, cnt + 0, l0);
    // 3. exact repair of flagged qk spikes
    repair_qk<<<512, 256>>>(xsT, q_w, k_w, q_g, q_b, k_g, k_b, qkT);
    // 4. attention -> y0T
    attn_kernel<<<(B_ * NN * 8) / 256, 256>>>(qkT, y0T, mem_alpha);
    // 5. proj hi-only: x1 = x + bn(proj@y0 + bias); z0T = lif(x1); flags
    gemm_mma<256, 256, 4, 0, 0><<<gPJ, 256, SMEM_SP>>>(pp, y0T, x1, z0T,
        proj_bias, proj_g, proj_b2, nullptr, nullptr, x, 1.f, cnt + 1, l1);
    // 6. exact repair of flagged proj elements (patches x1 AND z0 spikes)
    repair_pj<<<512, 256>>>(y0T, proj_w, proj_bias, proj_g, proj_b2, x, x1, z0T);
    // 7. w1 GEMM hi-only + bn1 + LIF + flags -> z1T
    gemm_mma<256, 1024, 3, 0, 0><<<gW1, 256, SMEM_SP>>>(pw1, z0T, nullptr, z1T,
        b1, bn1_g, bn1_b, nullptr, nullptr, nullptr, 1.f, cnt + 2, l2);
    // 8. exact repair of flagged z1 spikes
    repair_w1<<<512, 256>>>(z0T, w1, b1, bn1_g, bn1_b, z1T);
    // 9. out = x1 + bn2(w2@z1 + b2)  (hi-only, T-split)
    gemm_mma<1024, 256, 1, 0, 1><<<gW2, 256, SMEM_NF>>>(pw2, z1T, out, nullptr,
        b2, bn2_g, bn2_b, nullptr, nullptr, x1, 0.f, nullptr, nullptr);
}

// round 16
// speedup vs baseline: 1.0035x; 1.0035x over previous
#include <cuda_runtime.h>
#include <cuda_fp16.h>
#include <cstdint>

#define T_ 4
#define B_ 16
#define NN 1024
#define C_ 256
#define CH_ 1024
#define SC (B_*C_*NN)
#define SQK (B_*NN*512)
#define SCH (B_*CH_*NN)
#define FLCAP (1u<<21)
#define EPS_FLAG 4e-3f

// ---------------- scratch ----------------
__device__ __half g_xsT [(size_t)T_*SC];
__device__ __half g_qkT [(size_t)T_*SQK];
__device__ __half g_y0T [(size_t)T_*SC];
__device__ __half g_z0T [(size_t)T_*SC];
__device__ __half g_z1T [(size_t)T_*SCH];
__device__ __half g_x1h [(size_t)T_*SC];   // x1 stored fp16 (residual only)
__device__ __half g_pqk [512*256];    // hi only
__device__ __half g_pp  [256*256];    // hi only
__device__ __half g_pw1 [1024*256];   // hi only
__device__ __half g_pw2 [256*1024];   // hi only
__device__ uint32_t g_cnt[3];
__device__ uint32_t g_l0[FLCAP];
__device__ uint32_t g_l1[FLCAP];
__device__ uint32_t g_l2[FLCAP];

// ---------------- helpers ----------------
__device__ __forceinline__ uint32_t smem_u32(const void* p) {
    uint32_t a;
    asm("{ .reg .u64 t; cvta.to.shared.u64 t, %1; cvt.u32.u64 %0, t; }" : "=r"(a) : "l"(p));
    return a;
}
__device__ __forceinline__ void cpasync16(uint32_t dst, const void* src) {
    asm volatile("cp.async.cg.shared.global [%0], [%1], 16;" :: "r"(dst), "l"(src) : "memory");
}
__device__ __forceinline__ void cp_commit() { asm volatile("cp.async.commit_group;" ::: "memory"); }
template<int N> __device__ __forceinline__ void cp_wait() {
    asm volatile("cp.async.wait_group %0;" :: "n"(N) : "memory");
}
__device__ __forceinline__ void ldsm4(uint32_t& r0, uint32_t& r1, uint32_t& r2, uint32_t& r3, uint32_t addr) {
    asm volatile("ldmatrix.sync.aligned.m8n8.x4.shared.b16 {%0,%1,%2,%3}, [%4];"
                 : "=r"(r0), "=r"(r1), "=r"(r2), "=r"(r3) : "r"(addr));
}
__device__ __forceinline__ void mma16816(float* d, const uint32_t* a, uint32_t b0, uint32_t b1) {
    asm volatile("mma.sync.aligned.m16n8k16.row.col.f32.f16.f16.f32 "
                 "{%0,%1,%2,%3}, {%4,%5,%6,%7}, {%8,%9}, {%0,%1,%2,%3};"
                 : "+f"(d[0]), "+f"(d[1]), "+f"(d[2]), "+f"(d[3])
                 : "r"(a[0]), "r"(a[1]), "r"(a[2]), "r"(a[3]), "r"(b0), "r"(b1));
}

// packed-A element index: blocked 64(m) x 64(ke) fp16 tiles, SW128-swizzled.
__device__ __forceinline__ size_t blk_elem(int m, int ke, int nck) {
    int bm = m >> 6, rin = m & 63, kc = ke >> 6, c = ke & 63;
    uint32_t byte = (uint32_t)(rin * 128 + c * 2);
    byte ^= (byte >> 3) & 0x70;
    return ((size_t)bm * nck + kc) * 4096 + (byte >> 1);
}

// ---------------- fused prep: lif_t (blocks 0..2047) + weight pack (2048..4863) ----
__global__ void prep_kernel(const float* __restrict__ x,
                            const float* __restrict__ qw, const float* __restrict__ kw,
                            const float* __restrict__ pw, const float* __restrict__ w1,
                            const float* __restrict__ w2) {
    if (blockIdx.x < 2048) {
        __shared__ __half st[4][32][72];
        int id = blockIdx.x;
        int n0 = (id & 31) * 32, c0 = ((id >> 5) & 3) * 64, b = id >> 7;
        int nl = threadIdx.x & 31, cg = threadIdx.x >> 5;
#pragma unroll
        for (int pass = 0; pass < 8; pass++) {
            int cl = pass * 8 + cg;
            int c = c0 + cl;
            float mem = 0.f;
#pragma unroll
            for (int t = 0; t < T_; t++) {
                float v = mem * 0.5f + x[((size_t)(t * B_ + b) * C_ + c) * NN + n0 + nl];
                float sp = (v >= 1.0f) ? 1.f : 0.f;
                st[t][nl][cl] = __float2half(sp);
                mem = v * (1.f - sp);
            }
        }
        __syncthreads();
        int rr = threadIdx.x >> 1, hf = threadIdx.x & 1;
        int t = rr >> 5, n = rr & 31;
        size_t row = ((size_t)(t * B_ + b) * NN + n0 + n) * C_ + c0 + hf * 32;
        uint4* d = (uint4*)(g_xsT + row);
        const uint4* s = (const uint4*)(&st[t][n][hf * 32]);
#pragma unroll
        for (int i = 0; i < 4; i++) d[i] = s[i];
    } else {
        int pid = blockIdx.x - 2048;
        if (pid == 0 && threadIdx.x < 3) g_cnt[threadIdx.x] = 0;
        int idx = pid * 256 + threadIdx.x;
        if (idx < 131072) {
            int m = idx >> 8, k = idx & 255;
            float w = (m < 256) ? qw[m * 256 + k] : kw[(m - 256) * 256 + k];
            g_pqk[blk_elem(m, k, 4)] = __float2half(w);
        } else if (idx < 196608) {
            int i = idx - 131072; int m = i >> 8, k = i & 255;
            g_pp[blk_elem(m, k, 4)] = __float2half(pw[i]);
        } else if (idx < 458752) {
            int i = idx - 196608; int m = i >> 8, k = i & 255;
            g_pw1[blk_elem(m, k, 4)] = __float2half(w1[i]);
        } else if (idx < 720896) {
            int i = idx - 458752; int m = i >> 10, k = i & 1023;
            g_pw2[blk_elem(m, k, 16)] = __float2half(w2[i]);
        }
    }
}

// ---------------- attention: 2 threads per (b,n,h), EXACT (integer q-sums) ----
__global__ void attn_kernel(const __half* __restrict__ qk, __half* __restrict__ y,
                            const float* __restrict__ alpha_p) {
    int idx = blockIdx.x * 256 + threadIdx.x;  // (b,n,h,half), half = bit 0
    int half = idx & 1;
    int h = (idx >> 1) & 7;
    int n = (idx >> 4) & 1023;
    int b = idx >> 14;
    float alpha = *alpha_p;
    size_t baseq = ((size_t)(b * NN + n)) * 512 + h * 32;
    size_t basey = ((size_t)(b * NN + n)) * C_ + h * 32;

    float qs[T_];
#pragma unroll
    for (int t = 0; t < T_; t++) {
        const __half2* p = (const __half2*)(qk + (size_t)t * SQK + baseq + half * 16);
        float s = 0.f;
#pragma unroll
        for (int i = 0; i < 8; i++) {
            float2 f = __half22float2(p[i]);
            s += f.x + f.y;
        }
        // partner holds the other 16 elements; spike counts are integers -> exact
        s += __shfl_xor_sync(0xFFFFFFFFu, s, 1);
        qs[t] = s;
    }
    float ms[T_];
    ms[0] = qs[0];
#pragma unroll
    for (int t = 1; t < T_; t++) ms[t] = alpha * ms[t - 1] + (1.f - alpha) * qs[t - 1];

    float mem = 0.f;
#pragma unroll
    for (int t = 0; t < T_; t++) {
        float v = mem * 0.5f + (ms[t] + qs[t]);
        float sp = (v >= 0.5f) ? 1.f : 0.f;
        mem = v * (1.f - sp);
        const uint4* kp = (const uint4*)(qk + (size_t)t * SQK + baseq + 256) + half * 2;
        uint4* yp = (uint4*)(y + (size_t)t * SC + basey) + half * 2;
        if (sp != 0.f) { yp[0] = kp[0]; yp[1] = kp[1]; }
        else { uint4 z = {0, 0, 0, 0}; yp[0] = z; yp[1] = z; }
    }
}

// ---------------- exact repairs: one WARP per flagged element ----------------
__global__ void repair_qk(const __half* __restrict__ xsT,
                          const float* __restrict__ qw, const float* __restrict__ kw,
                          const float* __restrict__ qg, const float* __restrict__ qb,
                          const float* __restrict__ kg, const float* __restrict__ kb,
                          __half* __restrict__ qkT) {
    uint32_t cnt = g_cnt[0]; if (cnt > FLCAP) cnt = FLCAP;
    uint32_t gw = (blockIdx.x * 256 + threadIdx.x) >> 5;
    uint32_t nwarp = gridDim.x * 8;
    int lane = threadIdx.x & 31;
    for (uint32_t idx = gw; idx < cnt; idx += nwarp) {
        uint32_t pk = g_l0[idx];
        int b = pk >> 20, n = (pk >> 10) & 1023, m = pk & 1023;
        const float* wrow; float sc, sh;
        if (m < 256) { wrow = qw + (size_t)m * 256; sc = qg[m]; sh = qb[m]; }
        else         { wrow = kw + (size_t)(m - 256) * 256; sc = kg[m - 256]; sh = kb[m - 256]; }
        float4 w0 = *(const float4*)&wrow[lane * 8];
        float4 w1v = *(const float4*)&wrow[lane * 8 + 4];
        float mem = 0.f;
        for (int t = 0; t < T_; t++) {
            const __half2* xr = (const __half2*)(xsT + ((size_t)((t * B_ + b) * NN + n)) * C_) + lane * 4;
            float2 f0 = __half22float2(xr[0]);
            float2 f1 = __half22float2(xr[1]);
            float2 f2 = __half22float2(xr[2]);
            float2 f3 = __half22float2(xr[3]);
            float dot = f0.x * w0.x + f0.y * w0.y + f1.x * w0.z + f1.y * w0.w
                      + f2.x * w1v.x + f2.y * w1v.y + f3.x * w1v.z + f3.y * w1v.w;
#pragma unroll
            for (int o = 16; o; o >>= 1) dot += __shfl_xor_sync(0xFFFFFFFFu, dot, o);
            float v = dot * sc + sh;
            float u = mem * 0.5f + v;
            float sp = (u >= 1.f) ? 1.f : 0.f;
            mem = u * (1.f - sp);
            if (lane == 0)
                qkT[((size_t)((t * B_ + b) * NN + n)) * 512 + m] = __float2half(sp);
        }
    }
}

// proj repair: exact dot over y0T + bias/bn + x residual; patches x1h AND z0 spike.
__global__ void repair_pj(const __half* __restrict__ y0T, const float* __restrict__ pw,
                          const float* __restrict__ pbias,
                          const float* __restrict__ pg, const float* __restrict__ pb2,
                          const float* __restrict__ x,
                          __half* __restrict__ x1h, __half* __restrict__ z0T) {
    uint32_t cnt = g_cnt[1]; if (cnt > FLCAP) cnt = FLCAP;
    uint32_t gw = (blockIdx.x * 256 + threadIdx.x) >> 5;
    uint32_t nwarp = gridDim.x * 8;
    int lane = threadIdx.x & 31;
    for (uint32_t idx = gw; idx < cnt; idx += nwarp) {
        uint32_t pk = g_l1[idx];
        int b = pk >> 20, n = (pk >> 10) & 1023, m = pk & 1023;
        const float* wrow = pw + (size_t)m * 256;
        float pb = pbias[m], sc = pg[m], sh = pb2[m];
        float4 w0 = *(const float4*)&wrow[lane * 8];
        float4 w1v = *(const float4*)&wrow[lane * 8 + 4];
        float mem = 0.f;
        for (int t = 0; t < T_; t++) {
            const __half2* xr = (const __half2*)(y0T + ((size_t)((t * B_ + b) * NN + n)) * C_) + lane * 4;
            float2 f0 = __half22float2(xr[0]);
            float2 f1 = __half22float2(xr[1]);
            float2 f2 = __half22float2(xr[2]);
            float2 f3 = __half22float2(xr[3]);
            float dot = f0.x * w0.x + f0.y * w0.y + f1.x * w0.z + f1.y * w0.w
                      + f2.x * w1v.x + f2.y * w1v.y + f3.x * w1v.z + f3.y * w1v.w;
#pragma unroll
            for (int o = 16; o; o >>= 1) dot += __shfl_xor_sync(0xFFFFFFFFu, dot, o);
            size_t o = ((size_t)((t * B_ + b) * C_) + m) * NN + n;
            float v = (dot + pb) * sc + sh + x[o];
            float u = mem * 0.5f + v;
            float sp = (u >= 1.f) ? 1.f : 0.f;
            mem = u * (1.f - sp);
            if (lane == 0) {
                x1h[o] = __float2half(v);
                z0T[((size_t)((t * B_ + b) * NN + n)) * C_ + m] = __float2half(sp);
            }
        }
    }
}

__global__ void repair_w1(const __half* __restrict__ z0T, const float* __restrict__ w1,
                          const float* __restrict__ b1,
                          const float* __restrict__ g1, const float* __restrict__ bb1,
                          __half* __restrict__ z1T) {
    uint32_t cnt = g_cnt[2]; if (cnt > FLCAP) cnt = FLCAP;
    uint32_t gw = (blockIdx.x * 256 + threadIdx.x) >> 5;
    uint32_t nwarp = gridDim.x * 8;
    int lane = threadIdx.x & 31;
    for (uint32_t idx = gw; idx < cnt; idx += nwarp) {
        uint32_t pk = g_l2[idx];
        int b = pk >> 20, n = (pk >> 10) & 1023, m = pk & 1023;
        const float* wrow = w1 + (size_t)m * 256;
        float pb = b1[m], sc = g1[m], sh = bb1[m];
        float4 w0 = *(const float4*)&wrow[lane * 8];
        float4 w1v = *(const float4*)&wrow[lane * 8 + 4];
        float mem = 0.f;
        for (int t = 0; t < T_; t++) {
            const __half2* xr = (const __half2*)(z0T + ((size_t)((t * B_ + b) * NN + n)) * C_) + lane * 4;
            float2 f0 = __half22float2(xr[0]);
            float2 f1 = __half22float2(xr[1]);
            float2 f2 = __half22float2(xr[2]);
            float2 f3 = __half22float2(xr[3]);
            float dot = f0.x * w0.x + f0.y * w0.y + f1.x * w0.z + f1.y * w0.w
                      + f2.x * w1v.x + f2.y * w1v.y + f3.x * w1v.z + f3.y * w1v.w;
#pragma unroll
            for (int o = 16; o; o >>= 1) dot += __shfl_xor_sync(0xFFFFFFFFu, dot, o);
            float v = (dot + pb) * sc + sh;
            float u = mem * 0.5f + v;
            float sp = (u >= 1.f) ? 1.f : 0.f;
            mem = u * (1.f - sp);
            if (lane == 0)
                z1T[((size_t)((t * B_ + b) * NN + n)) * CH_ + m] = __float2half(sp);
        }
    }
}

// ---------------- fp16 HMMA GEMM, fused epilogues ----------------
// CTA 64(M) x 128(N); 8 warps 2m x 4n; 2 CTAs/SM; 3-stage 1-sync pipeline.
// EPI 1: affine + res -> output (w2). EPI 4: affine + res + f16 out + LIF + flags (proj).
// EPI 3: bn + LIF -> spikes + flags (qk, w1).
// F16X: EPI4 -> writes residual result as fp16 (outH); EPI1 -> reads res from fp16 (resH).
// TSPLIT: grid z = t*B_+b, single timestep per CTA (only legal when no LIF).
#define OF_B   24576
#define OF_STG 73728
#define SMEM_SP 93184
#define SMEM_NF 74752

template<int CSRC, int COUT, int EPI, int DUAL, int TSPLIT, int F16X>
__global__ __launch_bounds__(256, 2) void gemm_mma(
    const __half* __restrict__ pack, const __half* __restrict__ XT,
    float* __restrict__ outF, __half* __restrict__ outS,
    const float* __restrict__ bias1,
    const float* __restrict__ scale, const float* __restrict__ shift,
    const float* __restrict__ scale2, const float* __restrict__ shift2,
    const float* __restrict__ res, const __half* __restrict__ resH,
    __half* __restrict__ outH, float thr,
    uint32_t* flcnt, uint32_t* fllist)
{
    extern __shared__ char smraw[];
    uint32_t smb0 = smem_u32(smraw);
    uint32_t smb = (smb0 + 1023u) & ~1023u;
    char* base = smraw + (smb - smb0);

    const bool WR_F32 = (EPI == 1 || EPI == 4);
    const bool WR_SPK = (EPI != 1);
    const bool FLAGS  = (EPI >= 3);

    const int NC = CSRC / 64;
    const int TT = TSPLIT ? 1 : T_;
    const int G = TT * NC;
    const int n0g = blockIdx.x * 128;
    const int m0g = blockIdx.y * 64;
    const int zb  = blockIdx.z;
    const int b   = TSPLIT ? (zb & (B_ - 1)) : zb;
    const int t0  = TSPLIT ? (zb >> 4) : 0;
    const int tid = threadIdx.x;
    const int wid = tid >> 5, lane = tid & 31;
    const int mw = (wid >> 2) * 32, nw = (wid & 3) * 32;
    const int r = lane >> 2, qn = lane & 3;

    const float* SCp = scale; const float* SHp = shift; int moff = m0g;
    if (DUAL && m0g >= 256) { SCp = scale2; SHp = shift2; moff = m0g - 256; }

    float pb[2][2], psc[2][2], psh[2][2];
#pragma unroll
    for (int mi = 0; mi < 2; mi++)
#pragma unroll
        for (int h = 0; h < 2; h++) {
            int ml = mw + mi * 16 + r + h * 8;
            pb[mi][h]  = bias1 ? bias1[m0g + ml] : 0.f;
            psc[mi][h] = SCp[moff + ml];
            psh[mi][h] = SHp[moff + ml];
        }

    float acc[2][4][4];
    float memv[2][4][4];
    uint32_t bmask = 0;
#pragma unroll
    for (int mi = 0; mi < 2; mi++)
#pragma unroll
        for (int j = 0; j < 4; j++)
#pragma unroll
            for (int e = 0; e < 4; e++) { acc[mi][j][e] = 0.f; memv[mi][j][e] = 0.f; }

    auto issue = [&](int g) {
        int t = t0 + g / NC, kc = g % NC;
        int buf = g % 3;
        const __half* asrc = pack + ((size_t)blockIdx.y * NC + kc) * 4096 + tid * 16;
        uint32_t adst = smb + buf * 8192 + tid * 32;
        cpasync16(adst, asrc);
        cpasync16(adst + 16, asrc + 8);
        int row = tid >> 1, hf = tid & 1;
        const __half* bsrc = XT + ((size_t)((t * B_ + b) * NN + n0g + row)) * CSRC + kc * 64 + hf * 32;
        uint32_t bb = smb + OF_B + buf * 16384;
#pragma unroll
        for (int i = 0; i < 4; i++) {
            uint32_t byte = (uint32_t)(row * 128 + hf * 64 + i * 16);
            byte ^= ((byte >> 3) & 0x70);
            cpasync16(bb + byte, bsrc + i * 8);
        }
        cp_commit();
    };

    issue(0); issue(1);
    for (int g = 0; g < G; g++) {
        cp_wait<1>();
        __syncthreads();
        if (g + 2 < G) issue(g + 2); else cp_commit();

        uint32_t aB = smb + (g % 3) * 8192;
        uint32_t bB = smb + OF_B + (g % 3) * 16384;
#pragma unroll
        for (int ks = 0; ks < 4; ks++) {
            uint32_t af[2][4], bf[2][4];
#pragma unroll
            for (int mi = 0; mi < 2; mi++) {
                uint32_t byte = (uint32_t)((mw + mi * 16 + (lane & 15)) * 128 +
                                           (ks * 16 + (lane >> 4) * 8) * 2);
                byte ^= ((byte >> 3) & 0x70);
                ldsm4(af[mi][0], af[mi][1], af[mi][2], af[mi][3], aB + byte);
            }
#pragma unroll
            for (int j2 = 0; j2 < 2; j2++) {
                uint32_t byte = (uint32_t)((nw + j2 * 16 + (lane & 15)) * 128 +
                                           (ks * 16 + (lane >> 4) * 8) * 2);
                byte ^= ((byte >> 3) & 0x70);
                ldsm4(bf[j2][0], bf[j2][1], bf[j2][2], bf[j2][3], bB + byte);
            }
#pragma unroll
            for (int mi = 0; mi < 2; mi++)
#pragma unroll
                for (int j = 0; j < 4; j++)
                    mma16816(acc[mi][j], af[mi], bf[j >> 1][j & 1], bf[j >> 1][(j & 1) + 2]);
        }

        if ((g % NC) == NC - 1) {
            int t = t0 + g / NC;
#pragma unroll
            for (int mi = 0; mi < 2; mi++)
#pragma unroll
                for (int h = 0; h < 2; h++) {
                    int ml = mw + mi * 16 + r + h * 8;
#pragma unroll
                    for (int j = 0; j < 4; j++) {
#pragma unroll
                        for (int eo = 0; eo < 2; eo++) {
                            int e = h * 2 + eo;
                            int nl = nw + j * 8 + qn * 2 + eo;
                            float v = (acc[mi][j][e] + pb[mi][h]) * psc[mi][h] + psh[mi][h];
                            acc[mi][j][e] = 0.f;
                            if (WR_F32) {
                                size_t o = ((size_t)((t * B_ + b) * COUT) + m0g + ml) * NN
                                         + n0g + nl;
                                if (EPI == 1 && F16X) {
                                    v += __half2float(resH[o]);
                                    outF[o] = v;
                                } else if (EPI == 4 && F16X) {
                                    v += res[o];
                                    outH[o] = __float2half(v);
                                } else {
                                    v += res[o];
                                    outF[o] = v;
                                }
                            }
                            if (WR_SPK) {
                                float u = memv[mi][j][e] * 0.5f + v;
                                float sp = (u >= thr) ? 1.f : 0.f;
                                memv[mi][j][e] = u * (1.f - sp);
                                if (FLAGS && fabsf(u - thr) < EPS_FLAG)
                                    bmask |= 1u << (mi * 16 + j * 4 + e);
                                *(__half*)(base + OF_STG + nl * 144 + ml * 2) = __float2half(sp);
                            }
                        }
                    }
                }
            if (WR_SPK) {
                __syncthreads();
                int row = tid >> 1, hf = tid & 1;
                const uint4* s4 = (const uint4*)(base + OF_STG + row * 144 + hf * 64);
                uint4* d4 = (uint4*)(outS + ((size_t)((t * B_ + b) * NN + n0g + row)) * COUT
                                           + m0g + hf * 32);
#pragma unroll
                for (int i = 0; i < 4; i++) d4[i] = s4[i];
            }
            if (FLAGS && t == T_ - 1 && bmask) {
#pragma unroll
                for (int bit = 0; bit < 32; bit++)
                    if ((bmask >> bit) & 1) {
                        int mi = bit >> 4, j = (bit >> 2) & 3, e = bit & 3;
                        int h = e >> 1, eo = e & 1;
                        int ml = mw + mi * 16 + r + h * 8;
                        int nl = nw + j * 8 + qn * 2 + eo;
                        uint32_t pk = ((uint32_t)b << 20) | ((uint32_t)(n0g + nl) << 10)
                                    | (uint32_t)(m0g + ml);
                        uint32_t pos = atomicAdd(flcnt, 1u);
                        if (pos < FLCAP) fllist[pos] = pk;
                    }
            }
        }
    }
}

// ---------------- launch ----------------
extern "C" void kernel_launch(void* const* d_in, const int* in_sizes, int n_in,
                              void* d_out, int out_size) {
    const float* x         = (const float*)d_in[0];
    const float* q_w       = (const float*)d_in[1];
    const float* q_g       = (const float*)d_in[2];
    const float* q_b       = (const float*)d_in[3];
    const float* k_w       = (const float*)d_in[4];
    const float* k_g       = (const float*)d_in[5];
    const float* k_b       = (const float*)d_in[6];
    const float* proj_w    = (const float*)d_in[7];
    const float* proj_bias = (const float*)d_in[8];
    const float* proj_g    = (const float*)d_in[9];
    const float* proj_b2   = (const float*)d_in[10];
    const float* mem_alpha = (const float*)d_in[11];
    const float* w1        = (const float*)d_in[12];
    const float* b1        = (const float*)d_in[13];
    const float* bn1_g     = (const float*)d_in[14];
    const float* bn1_b     = (const float*)d_in[15];
    const float* w2        = (const float*)d_in[16];
    const float* b2        = (const float*)d_in[17];
    const float* bn2_g     = (const float*)d_in[18];
    const float* bn2_b     = (const float*)d_in[19];
    float* out = (float*)d_out;

    __half *xsT, *qkT, *y0T, *z0T, *z1T, *x1h, *pqk, *pp, *pw1, *pw2;
    uint32_t *cnt, *l0, *l1, *l2;
    cudaGetSymbolAddress((void**)&xsT, g_xsT);
    cudaGetSymbolAddress((void**)&qkT, g_qkT);
    cudaGetSymbolAddress((void**)&y0T, g_y0T);
    cudaGetSymbolAddress((void**)&z0T, g_z0T);
    cudaGetSymbolAddress((void**)&z1T, g_z1T);
    cudaGetSymbolAddress((void**)&x1h, g_x1h);
    cudaGetSymbolAddress((void**)&pqk, g_pqk);
    cudaGetSymbolAddress((void**)&pp,  g_pp);
    cudaGetSymbolAddress((void**)&pw1, g_pw1);
    cudaGetSymbolAddress((void**)&pw2, g_pw2);
    cudaGetSymbolAddress((void**)&cnt, g_cnt);
    cudaGetSymbolAddress((void**)&l0,  g_l0);
    cudaGetSymbolAddress((void**)&l1,  g_l1);
    cudaGetSymbolAddress((void**)&l2,  g_l2);

    cudaFuncSetAttribute(gemm_mma<256, 512, 3, 1, 0, 0>,  cudaFuncAttributeMaxDynamicSharedMemorySize, SMEM_SP);
    cudaFuncSetAttribute(gemm_mma<256, 256, 4, 0, 0, 1>,  cudaFuncAttributeMaxDynamicSharedMemorySize, SMEM_SP);
    cudaFuncSetAttribute(gemm_mma<256, 1024, 3, 0, 0, 0>, cudaFuncAttributeMaxDynamicSharedMemorySize, SMEM_SP);
    cudaFuncSetAttribute(gemm_mma<1024, 256, 1, 0, 1, 1>, cudaFuncAttributeMaxDynamicSharedMemorySize, SMEM_NF);

    dim3 gQK(8, 8, 16);
    dim3 gPJ(8, 4, 16);
    dim3 gW1(8, 16, 16);
    dim3 gW2(8, 4, 64);   // T-split

    // 1. fused prep: lif_t(x) + weight pack + counter reset
    prep_kernel<<<4864, 256>>>(x, q_w, k_w, proj_w, w1, w2);
    // 2. merged q|k GEMM hi-only + bn + LIF + flags
    gemm_mma<256, 512, 3, 1, 0, 0><<<gQK, 256, SMEM_SP>>>(pqk, xsT, nullptr, qkT,
        nullptr, q_g, q_b, k_g, k_b, nullptr, nullptr, nullptr, 1.f, cnt + 0, l0);
    // 3. exact repair of flagged qk spikes
    repair_qk<<<512, 256>>>(xsT, q_w, k_w, q_g, q_b, k_g, k_b, qkT);
    // 4. attention -> y0T (2-way split, exact)
    attn_kernel<<<(B_ * NN * 8 * 2) / 256, 256>>>(qkT, y0T, mem_alpha);
    // 5. proj hi-only: x1h = fp16(x + bn(proj@y0 + bias)); z0T = lif(.); flags
    gemm_mma<256, 256, 4, 0, 0, 1><<<gPJ, 256, SMEM_SP>>>(pp, y0T, nullptr, z0T,
        proj_bias, proj_g, proj_b2, nullptr, nullptr, x, nullptr, x1h, 1.f, cnt + 1, l1);
    // 6. exact repair of flagged proj elements (patches x1h AND z0 spikes)
    repair_pj<<<512, 256>>>(y0T, proj_w, proj_bias, proj_g, proj_b2, x, x1h, z0T);
    // 7. w1 GEMM hi-only + bn1 + LIF + flags -> z1T
    gemm_mma<256, 1024, 3, 0, 0, 0><<<gW1, 256, SMEM_SP>>>(pw1, z0T, nullptr, z1T,
        b1, bn1_g, bn1_b, nullptr, nullptr, nullptr, nullptr, nullptr, 1.f, cnt + 2, l2);
    // 8. exact repair of flagged z1 spikes
    repair_w1<<<512, 256>>>(z0T, w1, b1, bn1_g, bn1_b, z1T);
    // 9. out = x1h + bn2(w2@z1 + b2)  (hi-only, T-split, fp16 residual)
    gemm_mma<1024, 256, 1, 0, 1, 1><<<gW2, 256, SMEM_NF>>>(pw2, z1T, out, nullptr,
        b2, bn2_g, bn2_b, nullptr, nullptr, nullptr, x1h, nullptr, 0.f, nullptr, nullptr);
}

// round 17
// speedup vs baseline: 1.0461x; 1.0424x over previous
#include <cuda_runtime.h>
#include <cuda_fp16.h>
#include <cstdint>

#define T_ 4
#define B_ 16
#define NN 1024
#define C_ 256
#define CH_ 1024
#define SC (B_*C_*NN)
#define SQK (B_*NN*512)
#define FLCAP (1u<<21)
#define EPS_FLAG 4e-3f

// ---------------- scratch ----------------
__device__ __half g_xsT [(size_t)T_*SC];
__device__ __half g_qkT [(size_t)T_*SQK];
__device__ __half g_y0T [(size_t)T_*SC];
__device__ __half g_z0T [(size_t)T_*SC];
__device__ uint32_t g_z1b[(size_t)T_*B_*NN*32];   // z1 spikes, bit-packed (8MB)
__device__ __half g_x1h [(size_t)T_*SC];
__device__ __half g_pqk [512*256];    // hi only
__device__ __half g_pp  [256*256];    // hi only
__device__ __half g_pw1 [1024*256];   // hi only
__device__ __half g_pw2 [256*1024];   // hi only
__device__ uint32_t g_cnt[3];
__device__ uint32_t g_l0[FLCAP];
__device__ uint32_t g_l1[FLCAP];
__device__ uint32_t g_l2[FLCAP];

// ---------------- helpers ----------------
__device__ __forceinline__ uint32_t smem_u32(const void* p) {
    uint32_t a;
    asm("{ .reg .u64 t; cvta.to.shared.u64 t, %1; cvt.u32.u64 %0, t; }" : "=r"(a) : "l"(p));
    return a;
}
__device__ __forceinline__ void cpasync16(uint32_t dst, const void* src) {
    asm volatile("cp.async.cg.shared.global [%0], [%1], 16;" :: "r"(dst), "l"(src) : "memory");
}
__device__ __forceinline__ void cp_commit() { asm volatile("cp.async.commit_group;" ::: "memory"); }
template<int N> __device__ __forceinline__ void cp_wait() {
    asm volatile("cp.async.wait_group %0;" :: "n"(N) : "memory");
}
__device__ __forceinline__ void ldsm4(uint32_t& r0, uint32_t& r1, uint32_t& r2, uint32_t& r3, uint32_t addr) {
    asm volatile("ldmatrix.sync.aligned.m8n8.x4.shared.b16 {%0,%1,%2,%3}, [%4];"
                 : "=r"(r0), "=r"(r1), "=r"(r2), "=r"(r3) : "r"(addr));
}
__device__ __forceinline__ void mma16816(float* d, const uint32_t* a, uint32_t b0, uint32_t b1) {
    asm volatile("mma.sync.aligned.m16n8k16.row.col.f32.f16.f16.f32 "
                 "{%0,%1,%2,%3}, {%4,%5,%6,%7}, {%8,%9}, {%0,%1,%2,%3};"
                 : "+f"(d[0]), "+f"(d[1]), "+f"(d[2]), "+f"(d[3])
                 : "r"(a[0]), "r"(a[1]), "r"(a[2]), "r"(a[3]), "r"(b0), "r"(b1));
}

// packed-A element index: blocked 64(m) x 64(ke) fp16 tiles, SW128-swizzled.
__device__ __forceinline__ size_t blk_elem(int m, int ke, int nck) {
    int bm = m >> 6, rin = m & 63, kc = ke >> 6, c = ke & 63;
    uint32_t byte = (uint32_t)(rin * 128 + c * 2);
    byte ^= (byte >> 3) & 0x70;
    return ((size_t)bm * nck + kc) * 4096 + (byte >> 1);
}

// ---------------- fused prep: lif_t + weight pack ----------------
__global__ void prep_kernel(const float* __restrict__ x,
                            const float* __restrict__ qw, const float* __restrict__ kw,
                            const float* __restrict__ pw, const float* __restrict__ w1,
                            const float* __restrict__ w2) {
    if (blockIdx.x < 2048) {
        __shared__ __half st[4][32][72];
        int id = blockIdx.x;
        int n0 = (id & 31) * 32, c0 = ((id >> 5) & 3) * 64, b = id >> 7;
        int nl = threadIdx.x & 31, cg = threadIdx.x >> 5;
#pragma unroll
        for (int pass = 0; pass < 8; pass++) {
            int cl = pass * 8 + cg;
            int c = c0 + cl;
            float mem = 0.f;
#pragma unroll
            for (int t = 0; t < T_; t++) {
                float v = mem * 0.5f + x[((size_t)(t * B_ + b) * C_ + c) * NN + n0 + nl];
                float sp = (v >= 1.0f) ? 1.f : 0.f;
                st[t][nl][cl] = __float2half(sp);
                mem = v * (1.f - sp);
            }
        }
        __syncthreads();
        int rr = threadIdx.x >> 1, hf = threadIdx.x & 1;
        int t = rr >> 5, n = rr & 31;
        size_t row = ((size_t)(t * B_ + b) * NN + n0 + n) * C_ + c0 + hf * 32;
        uint4* d = (uint4*)(g_xsT + row);
        const uint4* s = (const uint4*)(&st[t][n][hf * 32]);
#pragma unroll
        for (int i = 0; i < 4; i++) d[i] = s[i];
    } else {
        int pid = blockIdx.x - 2048;
        if (pid == 0 && threadIdx.x < 3) g_cnt[threadIdx.x] = 0;
        int idx = pid * 256 + threadIdx.x;
        if (idx < 131072) {
            int m = idx >> 8, k = idx & 255;
            float w = (m < 256) ? qw[m * 256 + k] : kw[(m - 256) * 256 + k];
            g_pqk[blk_elem(m, k, 4)] = __float2half(w);
        } else if (idx < 196608) {
            int i = idx - 131072; int m = i >> 8, k = i & 255;
            g_pp[blk_elem(m, k, 4)] = __float2half(pw[i]);
        } else if (idx < 458752) {
            int i = idx - 196608; int m = i >> 8, k = i & 255;
            g_pw1[blk_elem(m, k, 4)] = __float2half(w1[i]);
        } else if (idx < 720896) {
            int i = idx - 458752; int m = i >> 10, k = i & 1023;
            g_pw2[blk_elem(m, k, 16)] = __float2half(w2[i]);
        }
    }
}

// ---------------- attention: 2 threads per (b,n,h), EXACT ----------------
__global__ void attn_kernel(const __half* __restrict__ qk, __half* __restrict__ y,
                            const float* __restrict__ alpha_p) {
    int idx = blockIdx.x * 256 + threadIdx.x;
    int half = idx & 1;
    int h = (idx >> 1) & 7;
    int n = (idx >> 4) & 1023;
    int b = idx >> 14;
    float alpha = *alpha_p;
    size_t baseq = ((size_t)(b * NN + n)) * 512 + h * 32;
    size_t basey = ((size_t)(b * NN + n)) * C_ + h * 32;

    float qs[T_];
#pragma unroll
    for (int t = 0; t < T_; t++) {
        const __half2* p = (const __half2*)(qk + (size_t)t * SQK + baseq + half * 16);
        float s = 0.f;
#pragma unroll
        for (int i = 0; i < 8; i++) {
            float2 f = __half22float2(p[i]);
            s += f.x + f.y;
        }
        s += __shfl_xor_sync(0xFFFFFFFFu, s, 1);
        qs[t] = s;
    }
    float ms[T_];
    ms[0] = qs[0];
#pragma unroll
    for (int t = 1; t < T_; t++) ms[t] = alpha * ms[t - 1] + (1.f - alpha) * qs[t - 1];

    float mem = 0.f;
#pragma unroll
    for (int t = 0; t < T_; t++) {
        float v = mem * 0.5f + (ms[t] + qs[t]);
        float sp = (v >= 0.5f) ? 1.f : 0.f;
        mem = v * (1.f - sp);
        const uint4* kp = (const uint4*)(qk + (size_t)t * SQK + baseq + 256) + half * 2;
        uint4* yp = (uint4*)(y + (size_t)t * SC + basey) + half * 2;
        if (sp != 0.f) { yp[0] = kp[0]; yp[1] = kp[1]; }
        else { uint4 z = {0, 0, 0, 0}; yp[0] = z; yp[1] = z; }
    }
}

// ---------------- exact repairs: one WARP per flagged element ----------------
__global__ void repair_qk(const __half* __restrict__ xsT,
                          const float* __restrict__ qw, const float* __restrict__ kw,
                          const float* __restrict__ qg, const float* __restrict__ qb,
                          const float* __restrict__ kg, const float* __restrict__ kb,
                          __half* __restrict__ qkT) {
    uint32_t cnt = g_cnt[0]; if (cnt > FLCAP) cnt = FLCAP;
    uint32_t gw = (blockIdx.x * 256 + threadIdx.x) >> 5;
    uint32_t nwarp = gridDim.x * 8;
    int lane = threadIdx.x & 31;
    for (uint32_t idx = gw; idx < cnt; idx += nwarp) {
        uint32_t pk = g_l0[idx];
        int b = pk >> 20, n = (pk >> 10) & 1023, m = pk & 1023;
        const float* wrow; float sc, sh;
        if (m < 256) { wrow = qw + (size_t)m * 256; sc = qg[m]; sh = qb[m]; }
        else         { wrow = kw + (size_t)(m - 256) * 256; sc = kg[m - 256]; sh = kb[m - 256]; }
        float4 w0 = *(const float4*)&wrow[lane * 8];
        float4 w1v = *(const float4*)&wrow[lane * 8 + 4];
        float mem = 0.f;
        for (int t = 0; t < T_; t++) {
            const __half2* xr = (const __half2*)(xsT + ((size_t)((t * B_ + b) * NN + n)) * C_) + lane * 4;
            float2 f0 = __half22float2(xr[0]);
            float2 f1 = __half22float2(xr[1]);
            float2 f2 = __half22float2(xr[2]);
            float2 f3 = __half22float2(xr[3]);
            float dot = f0.x * w0.x + f0.y * w0.y + f1.x * w0.z + f1.y * w0.w
                      + f2.x * w1v.x + f2.y * w1v.y + f3.x * w1v.z + f3.y * w1v.w;
#pragma unroll
            for (int o = 16; o; o >>= 1) dot += __shfl_xor_sync(0xFFFFFFFFu, dot, o);
            float v = dot * sc + sh;
            float u = mem * 0.5f + v;
            float sp = (u >= 1.f) ? 1.f : 0.f;
            mem = u * (1.f - sp);
            if (lane == 0)
                qkT[((size_t)((t * B_ + b) * NN + n)) * 512 + m] = __float2half(sp);
        }
    }
}

__global__ void repair_pj(const __half* __restrict__ y0T, const float* __restrict__ pw,
                          const float* __restrict__ pbias,
                          const float* __restrict__ pg, const float* __restrict__ pb2,
                          const float* __restrict__ x,
                          __half* __restrict__ x1h, __half* __restrict__ z0T) {
    uint32_t cnt = g_cnt[1]; if (cnt > FLCAP) cnt = FLCAP;
    uint32_t gw = (blockIdx.x * 256 + threadIdx.x) >> 5;
    uint32_t nwarp = gridDim.x * 8;
    int lane = threadIdx.x & 31;
    for (uint32_t idx = gw; idx < cnt; idx += nwarp) {
        uint32_t pk = g_l1[idx];
        int b = pk >> 20, n = (pk >> 10) & 1023, m = pk & 1023;
        const float* wrow = pw + (size_t)m * 256;
        float pb = pbias[m], sc = pg[m], sh = pb2[m];
        float4 w0 = *(const float4*)&wrow[lane * 8];
        float4 w1v = *(const float4*)&wrow[lane * 8 + 4];
        float mem = 0.f;
        for (int t = 0; t < T_; t++) {
            const __half2* xr = (const __half2*)(y0T + ((size_t)((t * B_ + b) * NN + n)) * C_) + lane * 4;
            float2 f0 = __half22float2(xr[0]);
            float2 f1 = __half22float2(xr[1]);
            float2 f2 = __half22float2(xr[2]);
            float2 f3 = __half22float2(xr[3]);
            float dot = f0.x * w0.x + f0.y * w0.y + f1.x * w0.z + f1.y * w0.w
                      + f2.x * w1v.x + f2.y * w1v.y + f3.x * w1v.z + f3.y * w1v.w;
#pragma unroll
            for (int o = 16; o; o >>= 1) dot += __shfl_xor_sync(0xFFFFFFFFu, dot, o);
            size_t o = ((size_t)((t * B_ + b) * C_) + m) * NN + n;
            float v = (dot + pb) * sc + sh + x[o];
            float u = mem * 0.5f + v;
            float sp = (u >= 1.f) ? 1.f : 0.f;
            mem = u * (1.f - sp);
            if (lane == 0) {
                x1h[o] = __float2half(v);
                z0T[((size_t)((t * B_ + b) * NN + n)) * C_ + m] = __float2half(sp);
            }
        }
    }
}

// repairs z1 spikes in the BIT-PACKED buffer (atomic set/clear of distinct bits).
__global__ void repair_w1(const __half* __restrict__ z0T, const float* __restrict__ w1,
                          const float* __restrict__ b1,
                          const float* __restrict__ g1, const float* __restrict__ bb1,
                          uint32_t* __restrict__ z1b) {
    uint32_t cnt = g_cnt[2]; if (cnt > FLCAP) cnt = FLCAP;
    uint32_t gw = (blockIdx.x * 256 + threadIdx.x) >> 5;
    uint32_t nwarp = gridDim.x * 8;
    int lane = threadIdx.x & 31;
    for (uint32_t idx = gw; idx < cnt; idx += nwarp) {
        uint32_t pk = g_l2[idx];
        int b = pk >> 20, n = (pk >> 10) & 1023, m = pk & 1023;
        const float* wrow = w1 + (size_t)m * 256;
        float pb = b1[m], sc = g1[m], sh = bb1[m];
        float4 w0 = *(const float4*)&wrow[lane * 8];
        float4 w1v = *(const float4*)&wrow[lane * 8 + 4];
        float mem = 0.f;
        for (int t = 0; t < T_; t++) {
            const __half2* xr = (const __half2*)(z0T + ((size_t)((t * B_ + b) * NN + n)) * C_) + lane * 4;
            float2 f0 = __half22float2(xr[0]);
            float2 f1 = __half22float2(xr[1]);
            float2 f2 = __half22float2(xr[2]);
            float2 f3 = __half22float2(xr[3]);
            float dot = f0.x * w0.x + f0.y * w0.y + f1.x * w0.z + f1.y * w0.w
                      + f2.x * w1v.x + f2.y * w1v.y + f3.x * w1v.z + f3.y * w1v.w;
#pragma unroll
            for (int o = 16; o; o >>= 1) dot += __shfl_xor_sync(0xFFFFFFFFu, dot, o);
            float v = (dot + pb) * sc + sh;
            float u = mem * 0.5f + v;
            float sp = (u >= 1.f) ? 1.f : 0.f;
            mem = u * (1.f - sp);
            if (lane == 0) {
                size_t wi = ((size_t)((t * B_ + b) * NN + n)) * 32 + (m >> 5);
                uint32_t bit = 1u << (m & 31);
                if (sp != 0.f) atomicOr(&z1b[wi], bit);
                else           atomicAnd(&z1b[wi], ~bit);
            }
        }
    }
}

// ---------------- fp16 HMMA GEMM, fused epilogues ----------------
// CTA 64(M) x 128(N); 8 warps 2m x 4n; 2 CTAs/SM; 3-stage 1-sync pipeline.
// EPI 1: affine + resH -> fp32 out (w2). EPI 3: bn + LIF + flags -> spikes (qk, w1).
// EPI 4: affine + res + fp16 out + LIF + flags (proj).
// PACKB: EPI3 writes spikes BIT-PACKED (w1).  BITB: B operand read from bitmask (w2).
// TSPLIT: grid z = t*B_+b (no LIF chain only).
#define OF_B   24576
#define OF_STG 73728
#define SMEM_SP 93184
#define SMEM_NF 74752

template<int CSRC, int COUT, int EPI, int DUAL, int TSPLIT, int F16X, int PACKB, int BITB>
__global__ __launch_bounds__(256, 2) void gemm_mma(
    const __half* __restrict__ pack, const __half* __restrict__ XT,
    const uint32_t* __restrict__ XB,
    float* __restrict__ outF, __half* __restrict__ outS, uint32_t* __restrict__ outB,
    const float* __restrict__ bias1,
    const float* __restrict__ scale, const float* __restrict__ shift,
    const float* __restrict__ scale2, const float* __restrict__ shift2,
    const float* __restrict__ res, const __half* __restrict__ resH,
    __half* __restrict__ outH, float thr,
    uint32_t* flcnt, uint32_t* fllist)
{
    extern __shared__ char smraw[];
    uint32_t smb0 = smem_u32(smraw);
    uint32_t smb = (smb0 + 1023u) & ~1023u;
    char* base = smraw + (smb - smb0);

    const bool WR_F32 = (EPI == 1 || EPI == 4);
    const bool WR_SPK = (EPI != 1);
    const bool FLAGS  = (EPI >= 3);

    const int NC = CSRC / 64;
    const int TT = TSPLIT ? 1 : T_;
    const int G = TT * NC;
    const int n0g = blockIdx.x * 128;
    const int m0g = blockIdx.y * 64;
    const int zb  = blockIdx.z;
    const int b   = TSPLIT ? (zb & (B_ - 1)) : zb;
    const int t0  = TSPLIT ? (zb >> 4) : 0;
    const int tid = threadIdx.x;
    const int wid = tid >> 5, lane = tid & 31;
    const int mw = (wid >> 2) * 32, nw = (wid & 3) * 32;
    const int r = lane >> 2, qn = lane & 3;

    const float* SCp = scale; const float* SHp = shift; int moff = m0g;
    if (DUAL && m0g >= 256) { SCp = scale2; SHp = shift2; moff = m0g - 256; }

    float pb[2][2], psc[2][2], psh[2][2];
#pragma unroll
    for (int mi = 0; mi < 2; mi++)
#pragma unroll
        for (int h = 0; h < 2; h++) {
            int ml = mw + mi * 16 + r + h * 8;
            pb[mi][h]  = bias1 ? bias1[m0g + ml] : 0.f;
            psc[mi][h] = SCp[moff + ml];
            psh[mi][h] = SHp[moff + ml];
        }

    float acc[2][4][4];
    float memv[2][4][4];
    uint32_t bmask = 0;
#pragma unroll
    for (int mi = 0; mi < 2; mi++)
#pragma unroll
        for (int j = 0; j < 4; j++)
#pragma unroll
            for (int e = 0; e < 4; e++) { acc[mi][j][e] = 0.f; memv[mi][j][e] = 0.f; }

    auto issue = [&](int g) {
        int t = t0 + g / NC, kc = g % NC;
        int buf = g % 3;
        const __half* asrc = pack + ((size_t)blockIdx.y * NC + kc) * 4096 + tid * 16;
        uint32_t adst = smb + buf * 8192 + tid * 32;
        cpasync16(adst, asrc);
        cpasync16(adst + 16, asrc + 8);
        int row = tid >> 1, hf = tid & 1;
        uint32_t bb = smb + OF_B + buf * 16384;
        if (BITB) {
            // expand 32 spike bits -> 64B of fp16 {0,1} at swizzled positions
            uint32_t wv = XB[((size_t)((t * B_ + b) * NN + n0g + row)) * 32 + kc * 2 + hf];
#pragma unroll
            for (int i4 = 0; i4 < 4; i4++) {
                uint4 v;
                uint32_t bs = wv >> (i4 * 8);
                v.x = ((bs & 1u) ? 0x3C00u : 0u) | ((bs & 2u) ? 0x3C000000u : 0u);
                v.y = ((bs & 4u) ? 0x3C00u : 0u) | ((bs & 8u) ? 0x3C000000u : 0u);
                v.z = ((bs & 16u) ? 0x3C00u : 0u) | ((bs & 32u) ? 0x3C000000u : 0u);
                v.w = ((bs & 64u) ? 0x3C00u : 0u) | ((bs & 128u) ? 0x3C000000u : 0u);
                uint32_t byte = (uint32_t)(row * 128 + hf * 64 + i4 * 16);
                byte ^= ((byte >> 3) & 0x70);
                *(uint4*)(base + (OF_B + buf * 16384 - 0) + byte) = v;
            }
        } else {
            const __half* bsrc = XT + ((size_t)((t * B_ + b) * NN + n0g + row)) * CSRC + kc * 64 + hf * 32;
#pragma unroll
            for (int i = 0; i < 4; i++) {
                uint32_t byte = (uint32_t)(row * 128 + hf * 64 + i * 16);
                byte ^= ((byte >> 3) & 0x70);
                cpasync16(bb + byte, bsrc + i * 8);
            }
        }
        cp_commit();
    };

    issue(0); issue(1);
    for (int g = 0; g < G; g++) {
        cp_wait<1>();
        __syncthreads();
        if (g + 2 < G) issue(g + 2); else cp_commit();

        uint32_t aB = smb + (g % 3) * 8192;
        uint32_t bB = smb + OF_B + (g % 3) * 16384;
#pragma unroll
        for (int ks = 0; ks < 4; ks++) {
            uint32_t af[2][4], bf[2][4];
#pragma unroll
            for (int mi = 0; mi < 2; mi++) {
                uint32_t byte = (uint32_t)((mw + mi * 16 + (lane & 15)) * 128 +
                                           (ks * 16 + (lane >> 4) * 8) * 2);
                byte ^= ((byte >> 3) & 0x70);
                ldsm4(af[mi][0], af[mi][1], af[mi][2], af[mi][3], aB + byte);
            }
#pragma unroll
            for (int j2 = 0; j2 < 2; j2++) {
                uint32_t byte = (uint32_t)((nw + j2 * 16 + (lane & 15)) * 128 +
                                           (ks * 16 + (lane >> 4) * 8) * 2);
                byte ^= ((byte >> 3) & 0x70);
                ldsm4(bf[j2][0], bf[j2][1], bf[j2][2], bf[j2][3], bB + byte);
            }
#pragma unroll
            for (int mi = 0; mi < 2; mi++)
#pragma unroll
                for (int j = 0; j < 4; j++)
                    mma16816(acc[mi][j], af[mi], bf[j >> 1][j & 1], bf[j >> 1][(j & 1) + 2]);
        }

        if ((g % NC) == NC - 1) {
            int t = t0 + g / NC;
#pragma unroll
            for (int mi = 0; mi < 2; mi++)
#pragma unroll
                for (int h = 0; h < 2; h++) {
                    int ml = mw + mi * 16 + r + h * 8;
#pragma unroll
                    for (int j = 0; j < 4; j++) {
#pragma unroll
                        for (int eo = 0; eo < 2; eo++) {
                            int e = h * 2 + eo;
                            int nl = nw + j * 8 + qn * 2 + eo;
                            float v = (acc[mi][j][e] + pb[mi][h]) * psc[mi][h] + psh[mi][h];
                            acc[mi][j][e] = 0.f;
                            if (WR_F32) {
                                size_t o = ((size_t)((t * B_ + b) * COUT) + m0g + ml) * NN
                                         + n0g + nl;
                                if (EPI == 1 && F16X) {
                                    v += __half2float(resH[o]);
                                    outF[o] = v;
                                } else if (EPI == 4 && F16X) {
                                    v += res[o];
                                    outH[o] = __float2half(v);
                                } else {
                                    v += res[o];
                                    outF[o] = v;
                                }
                            }
                            if (WR_SPK) {
                                float u = memv[mi][j][e] * 0.5f + v;
                                float sp = (u >= thr) ? 1.f : 0.f;
                                memv[mi][j][e] = u * (1.f - sp);
                                if (FLAGS && fabsf(u - thr) < EPS_FLAG)
                                    bmask |= 1u << (mi * 16 + j * 4 + e);
                                if (PACKB)
                                    *(uint8_t*)(base + OF_STG + nl * 80 + ml) = (uint8_t)(sp != 0.f);
                                else
                                    *(__half*)(base + OF_STG + nl * 144 + ml * 2) = __float2half(sp);
                            }
                        }
                    }
                }
            if (WR_SPK) {
                __syncthreads();
                int row = tid >> 1, hf = tid & 1;
                if (PACKB) {
                    // build uint32 of 32 spike bits (bytes at [row*80 + hf*32 .. +31])
                    const uint4* s4 = (const uint4*)(base + OF_STG + row * 80 + hf * 32);
                    uint4 a0 = s4[0], a1 = s4[1];
                    uint32_t w[8] = {a0.x, a0.y, a0.z, a0.w, a1.x, a1.y, a1.z, a1.w};
                    uint32_t bits = 0;
#pragma unroll
                    for (int jw = 0; jw < 8; jw++)
#pragma unroll
                        for (int k = 0; k < 4; k++)
                            bits |= ((w[jw] >> (8 * k)) & 1u) << (jw * 4 + k);
                    outB[((size_t)((t * B_ + b) * NN + n0g + row)) * 32 + (m0g >> 5) + hf] = bits;
                } else {
                    const uint4* s4 = (const uint4*)(base + OF_STG + row * 144 + hf * 64);
                    uint4* d4 = (uint4*)(outS + ((size_t)((t * B_ + b) * NN + n0g + row)) * COUT
                                               + m0g + hf * 32);
#pragma unroll
                    for (int i = 0; i < 4; i++) d4[i] = s4[i];
                }
            }
            if (FLAGS && t == T_ - 1 && bmask) {
#pragma unroll
                for (int bit = 0; bit < 32; bit++)
                    if ((bmask >> bit) & 1) {
                        int mi = bit >> 4, j = (bit >> 2) & 3, e = bit & 3;
                        int h = e >> 1, eo = e & 1;
                        int ml = mw + mi * 16 + r + h * 8;
                        int nl = nw + j * 8 + qn * 2 + eo;
                        uint32_t pk = ((uint32_t)b << 20) | ((uint32_t)(n0g + nl) << 10)
                                    | (uint32_t)(m0g + ml);
                        uint32_t pos = atomicAdd(flcnt, 1u);
                        if (pos < FLCAP) fllist[pos] = pk;
                    }
            }
        }
    }
}

// ---------------- launch ----------------
extern "C" void kernel_launch(void* const* d_in, const int* in_sizes, int n_in,
                              void* d_out, int out_size) {
    const float* x         = (const float*)d_in[0];
    const float* q_w       = (const float*)d_in[1];
    const float* q_g       = (const float*)d_in[2];
    const float* q_b       = (const float*)d_in[3];
    const float* k_w       = (const float*)d_in[4];
    const float* k_g       = (const float*)d_in[5];
    const float* k_b       = (const float*)d_in[6];
    const float* proj_w    = (const float*)d_in[7];
    const float* proj_bias = (const float*)d_in[8];
    const float* proj_g    = (const float*)d_in[9];
    const float* proj_b2   = (const float*)d_in[10];
    const float* mem_alpha = (const float*)d_in[11];
    const float* w1        = (const float*)d_in[12];
    const float* b1        = (const float*)d_in[13];
    const float* bn1_g     = (const float*)d_in[14];
    const float* bn1_b     = (const float*)d_in[15];
    const float* w2        = (const float*)d_in[16];
    const float* b2        = (const float*)d_in[17];
    const float* bn2_g     = (const float*)d_in[18];
    const float* bn2_b     = (const float*)d_in[19];
    float* out = (float*)d_out;

    __half *xsT, *qkT, *y0T, *z0T, *x1h, *pqk, *pp, *pw1, *pw2;
    uint32_t *z1b, *cnt, *l0, *l1, *l2;
    cudaGetSymbolAddress((void**)&xsT, g_xsT);
    cudaGetSymbolAddress((void**)&qkT, g_qkT);
    cudaGetSymbolAddress((void**)&y0T, g_y0T);
    cudaGetSymbolAddress((void**)&z0T, g_z0T);
    cudaGetSymbolAddress((void**)&z1b, g_z1b);
    cudaGetSymbolAddress((void**)&x1h, g_x1h);
    cudaGetSymbolAddress((void**)&pqk, g_pqk);
    cudaGetSymbolAddress((void**)&pp,  g_pp);
    cudaGetSymbolAddress((void**)&pw1, g_pw1);
    cudaGetSymbolAddress((void**)&pw2, g_pw2);
    cudaGetSymbolAddress((void**)&cnt, g_cnt);
    cudaGetSymbolAddress((void**)&l0,  g_l0);
    cudaGetSymbolAddress((void**)&l1,  g_l1);
    cudaGetSymbolAddress((void**)&l2,  g_l2);

    cudaFuncSetAttribute(gemm_mma<256, 512, 3, 1, 0, 0, 0, 0>,  cudaFuncAttributeMaxDynamicSharedMemorySize, SMEM_SP);
    cudaFuncSetAttribute(gemm_mma<256, 256, 4, 0, 0, 1, 0, 0>,  cudaFuncAttributeMaxDynamicSharedMemorySize, SMEM_SP);
    cudaFuncSetAttribute(gemm_mma<256, 1024, 3, 0, 0, 0, 1, 0>, cudaFuncAttributeMaxDynamicSharedMemorySize, SMEM_SP);
    cudaFuncSetAttribute(gemm_mma<1024, 256, 1, 0, 1, 1, 0, 1>, cudaFuncAttributeMaxDynamicSharedMemorySize, SMEM_NF);

    dim3 gQK(8, 8, 16);
    dim3 gPJ(8, 4, 16);
    dim3 gW1(8, 16, 16);
    dim3 gW2(8, 4, 64);

    // 1. fused prep
    prep_kernel<<<4864, 256>>>(x, q_w, k_w, proj_w, w1, w2);
    // 2. merged q|k GEMM hi-only + bn + LIF + flags
    gemm_mma<256, 512, 3, 1, 0, 0, 0, 0><<<gQK, 256, SMEM_SP>>>(pqk, xsT, nullptr,
        nullptr, qkT, nullptr, nullptr, q_g, q_b, k_g, k_b,
        nullptr, nullptr, nullptr, 1.f, cnt + 0, l0);
    // 3. repair qk
    repair_qk<<<512, 256>>>(xsT, q_w, k_w, q_g, q_b, k_g, k_b, qkT);
    // 4. attention
    attn_kernel<<<(B_ * NN * 8 * 2) / 256, 256>>>(qkT, y0T, mem_alpha);
    // 5. proj hi-only: x1h + z0 spikes + flags
    gemm_mma<256, 256, 4, 0, 0, 1, 0, 0><<<gPJ, 256, SMEM_SP>>>(pp, y0T, nullptr,
        nullptr, z0T, nullptr, proj_bias, proj_g, proj_b2, nullptr, nullptr,
        x, nullptr, x1h, 1.f, cnt + 1, l1);
    // 6. repair proj (x1h + z0)
    repair_pj<<<512, 256>>>(y0T, proj_w, proj_bias, proj_g, proj_b2, x, x1h, z0T);
    // 7. w1 GEMM hi-only + bn1 + LIF + flags -> z1 BIT-PACKED
    gemm_mma<256, 1024, 3, 0, 0, 0, 1, 0><<<gW1, 256, SMEM_SP>>>(pw1, z0T, nullptr,
        nullptr, nullptr, z1b, b1, bn1_g, bn1_b, nullptr, nullptr,
        nullptr, nullptr, nullptr, 1.f, cnt + 2, l2);
    // 8. repair z1 (atomic bit patch)
    repair_w1<<<512, 256>>>(z0T, w1, b1, bn1_g, bn1_b, z1b);
    // 9. w2: out = x1h + bn2(w2@z1 + b2)  (B from bitmask, T-split)
    gemm_mma<1024, 256, 1, 0, 1, 1, 0, 1><<<gW2, 256, SMEM_NF>>>(pw2, nullptr, z1b,
        out, nullptr, nullptr, b2, bn2_g, bn2_b, nullptr, nullptr,
        nullptr, x1h, nullptr, 0.f, nullptr, nullptr);
}